// round 6
// baseline (speedup 1.0000x reference)
#include <cuda_runtime.h>
#include <cuda_bf16.h>
#include <math.h>
#include <stdint.h>

// Problem constants (B=1)
#define T 2048
#define H 1024
#define II 4096
#define E 8

// Tiling
#define BM 128
#define BN 128
#define KC 32              // K elems (bf16) per chunk
#define RSB 80             // smem row stride bytes (64B data + 16B pad)
#define STAGES 3
#define NTHREADS 512

#define TILE_B (BM * RSB)                      // 10240 B
#define STG_B  (4 * TILE_B)                    // Ah, Al, Bh, Bl = 40960 B
#define SM_TOK   0
#define SM_TILES 1024
#define OFF_T(s, t) (SM_TILES + (s) * STG_B + (t) * TILE_B)
#define SMEM_TOTAL (SM_TILES + STAGES * STG_B)   // 123904 B

// ---------------- scratch (device globals) ----------------
__device__ int   g_cnt[E];
__device__ int   g_off[E];
__device__ int   g_tok[E][T];
__device__ float g_wt[E][T];
__device__ __nv_bfloat16 g_xh[(size_t)T * H];
__device__ __nv_bfloat16 g_xl[(size_t)T * H];
__device__ __nv_bfloat16 g_w1h[(size_t)E * II * H];
__device__ __nv_bfloat16 g_w1l[(size_t)E * II * H];
__device__ __nv_bfloat16 g_w2h[(size_t)E * H * II];
__device__ __nv_bfloat16 g_w2l[(size_t)E * H * II];
__device__ __nv_bfloat16 g_hid_hi[(size_t)2 * T * II];
__device__ __nv_bfloat16 g_hid_lo[(size_t)2 * T * II];

// ---------------- helpers ----------------
__device__ __forceinline__ uint32_t smem_u32(const void* p) {
    uint32_t a;
    asm("{ .reg .u64 t; cvta.to.shared.u64 t, %1; cvt.u32.u64 %0, t; }" : "=r"(a) : "l"(p));
    return a;
}
__device__ __forceinline__ void cp16(uint32_t s, const void* g) {
    asm volatile("cp.async.cg.shared.global [%0], [%1], 16;" :: "r"(s), "l"(g));
}
__device__ __forceinline__ void cp_commit() {
    asm volatile("cp.async.commit_group;" ::: "memory");
}
template <int N>
__device__ __forceinline__ void cp_wait() {
    asm volatile("cp.async.wait_group %0;" :: "n"(N) : "memory");
}
__device__ __forceinline__ void ldsm4(uint32_t* r, uint32_t addr) {
    asm volatile("ldmatrix.sync.aligned.m8n8.x4.shared.b16 {%0,%1,%2,%3}, [%4];"
                 : "=r"(r[0]), "=r"(r[1]), "=r"(r[2]), "=r"(r[3]) : "r"(addr));
}
__device__ __forceinline__ void mma16816(float* d, const uint32_t* a, const uint32_t* b) {
    asm volatile("mma.sync.aligned.m16n8k16.row.col.f32.bf16.bf16.f32 "
                 "{%0,%1,%2,%3}, {%4,%5,%6,%7}, {%8,%9}, {%0,%1,%2,%3};"
                 : "+f"(d[0]), "+f"(d[1]), "+f"(d[2]), "+f"(d[3])
                 : "r"(a[0]), "r"(a[1]), "r"(a[2]), "r"(a[3]), "r"(b[0]), "r"(b[1]));
}
__device__ __forceinline__ void split4(float4 v, uint2& hi, uint2& lo) {
    float f0 = v.x, f1 = v.y, f2 = v.z, f3 = v.w;
    unsigned h0 = __bfloat16_as_ushort(__float2bfloat16(f0));
    unsigned h1 = __bfloat16_as_ushort(__float2bfloat16(f1));
    unsigned h2 = __bfloat16_as_ushort(__float2bfloat16(f2));
    unsigned h3 = __bfloat16_as_ushort(__float2bfloat16(f3));
    float r0 = f0 - __bfloat162float(__ushort_as_bfloat16((unsigned short)h0));
    float r1 = f1 - __bfloat162float(__ushort_as_bfloat16((unsigned short)h1));
    float r2 = f2 - __bfloat162float(__ushort_as_bfloat16((unsigned short)h2));
    float r3 = f3 - __bfloat162float(__ushort_as_bfloat16((unsigned short)h3));
    unsigned l0 = __bfloat16_as_ushort(__float2bfloat16(r0));
    unsigned l1 = __bfloat16_as_ushort(__float2bfloat16(r1));
    unsigned l2 = __bfloat16_as_ushort(__float2bfloat16(r2));
    unsigned l3 = __bfloat16_as_ushort(__float2bfloat16(r3));
    hi.x = h0 | (h1 << 16); hi.y = h2 | (h3 << 16);
    lo.x = l0 | (l1 << 16); lo.y = l2 | (l3 << 16);
}
__device__ __forceinline__ void split2(float a, float b, uint32_t& hi, uint32_t& lo) {
    unsigned ha = __bfloat16_as_ushort(__float2bfloat16(a));
    unsigned hb = __bfloat16_as_ushort(__float2bfloat16(b));
    float ra = a - __bfloat162float(__ushort_as_bfloat16((unsigned short)ha));
    float rb = b - __bfloat162float(__ushort_as_bfloat16((unsigned short)hb));
    unsigned la = __bfloat16_as_ushort(__float2bfloat16(ra));
    unsigned lb = __bfloat16_as_ushort(__float2bfloat16(rb));
    hi = ha | (hb << 16);
    lo = la | (lb << 16);
}

// ---------------- kernel: fp32 -> bf16 hi/lo split ----------------
__global__ void split_kernel(const float* __restrict__ src,
                             __nv_bfloat16* __restrict__ hi,
                             __nv_bfloat16* __restrict__ lo, int n4) {
    int i = blockIdx.x * blockDim.x + threadIdx.x;
    if (i < n4) {
        float4 v = ((const float4*)src)[i];
        uint2 h, l;
        split4(v, h, l);
        ((uint2*)hi)[i] = h;
        ((uint2*)lo)[i] = l;
    }
}

// ---------------- kernel 0: zero output + counters ----------------
__global__ void zero_kernel(float* __restrict__ out) {
    int i = blockIdx.x * blockDim.x + threadIdx.x;
    if (i < T * H) out[i] = 0.f;
    if (i < E) g_cnt[i] = 0;
}

// ---------------- kernel 1: gate -> top2 -> grouped lists ----------------
__global__ __launch_bounds__(256) void gate_kernel(const float* __restrict__ x,
                                                   const float* __restrict__ gw) {
    int t = blockIdx.x;
    int warp = threadIdx.x >> 5;
    int lane = threadIdx.x & 31;

    const float4* xr = (const float4*)(x + (size_t)t * H);
    const float4* gr = (const float4*)(gw + (size_t)warp * H);
    float s = 0.f;
    for (int j = lane; j < H / 4; j += 32) {
        float4 a = xr[j], b = gr[j];
        s += a.x * b.x + a.y * b.y + a.z * b.z + a.w * b.w;
    }
    #pragma unroll
    for (int o = 16; o > 0; o >>= 1) s += __shfl_xor_sync(0xffffffffu, s, o);

    __shared__ float lg[E];
    if (lane == 0) lg[warp] = s;
    __syncthreads();

    if (threadIdx.x == 0) {
        int e0 = 0;
        #pragma unroll
        for (int e = 1; e < E; e++) if (lg[e] > lg[e0]) e0 = e;
        int e1 = -1;
        #pragma unroll
        for (int e = 0; e < E; e++) {
            if (e == e0) continue;
            if (e1 < 0 || lg[e] > lg[e1]) e1 = e;
        }
        float d = expf(lg[e1] - lg[e0]);
        float w0 = 1.f / (1.f + d);
        float w1v = d / (1.f + d);
        int p0 = atomicAdd(&g_cnt[e0], 1);
        g_tok[e0][p0] = t; g_wt[e0][p0] = w0;
        int p1 = atomicAdd(&g_cnt[e1], 1);
        g_tok[e1][p1] = t; g_wt[e1][p1] = w1v;
    }
}

__global__ void prefix_kernel() {
    if (threadIdx.x == 0 && blockIdx.x == 0) {
        int acc = 0;
        #pragma unroll
        for (int e = 0; e < E; e++) { g_off[e] = acc; acc += g_cnt[e]; }
    }
}

// ---------------- mainloop mma over one stage (32x32 warp tile) ----------------
__device__ __forceinline__ void mma_stage(uint32_t sb, int stage, int warp_m, int warp_n,
                                          int lane, float (*acc)[4][4]) {
    int lr = lane & 15;
    uint32_t lc16 = (lane >> 4) * 16;
    uint32_t ah_b = sb + OFF_T(stage, 0), al_b = sb + OFF_T(stage, 1);
    uint32_t bh_b = sb + OFF_T(stage, 2), bl_b = sb + OFF_T(stage, 3);
    #pragma unroll
    for (int kk = 0; kk < 2; kk++) {
        uint32_t colb = kk * 32 + lc16;
        uint32_t Ah[2][4], Al[2][4], Bh[4][2], Bl[4][2];
        #pragma unroll
        for (int im = 0; im < 2; im++) {
            uint32_t aoff = (uint32_t)(warp_m * 32 + im * 16 + lr) * RSB + colb;
            ldsm4(Ah[im], ah_b + aoff);
            ldsm4(Al[im], al_b + aoff);
        }
        #pragma unroll
        for (int in2 = 0; in2 < 2; in2++) {
            uint32_t boff = (uint32_t)(warp_n * 32 + in2 * 16 + lr) * RSB + colb;
            uint32_t t[4];
            ldsm4(t, bh_b + boff);
            Bh[2 * in2][0] = t[0]; Bh[2 * in2][1] = t[2];
            Bh[2 * in2 + 1][0] = t[1]; Bh[2 * in2 + 1][1] = t[3];
            ldsm4(t, bl_b + boff);
            Bl[2 * in2][0] = t[0]; Bl[2 * in2][1] = t[2];
            Bl[2 * in2 + 1][0] = t[1]; Bl[2 * in2 + 1][1] = t[3];
        }
        #pragma unroll
        for (int im = 0; im < 2; im++)
            #pragma unroll
            for (int in = 0; in < 4; in++) {
                mma16816(acc[im][in], Ah[im], Bh[in]);
                mma16816(acc[im][in], Ah[im], Bl[in]);
                mma16816(acc[im][in], Al[im], Bh[in]);
            }
    }
}

// ---------------- kernel 2: grouped GEMM1 + silu ----------------
__global__ __launch_bounds__(NTHREADS, 1) void gemm1_tc() {
    extern __shared__ char smem[];
    int e = blockIdx.z;
    int cnt = g_cnt[e];
    int m0 = blockIdx.y * BM;
    if (m0 >= cnt) return;
    int n0 = blockIdx.x * BN;
    int base = g_off[e];
    int tid = threadIdx.x, wid = tid >> 5, lane = tid & 31;

    int* stok = (int*)(smem + SM_TOK);
    if (tid < BM) {
        int m = m0 + tid;
        stok[tid] = g_tok[e][m < cnt ? m : cnt - 1];
    }
    __syncthreads();
    uint32_t sb = smem_u32(smem);

    // staging: thread -> row = tid/4 (0..127), quarter = tid&3 -> one 16B cp per tile
    int row = tid >> 2, quarter = tid & 3;
    const __nv_bfloat16* ah = g_xh + (size_t)stok[row] * H + quarter * 8;
    const __nv_bfloat16* al = g_xl + (size_t)stok[row] * H + quarter * 8;
    const __nv_bfloat16* bh = g_w1h + (size_t)e * II * H + (size_t)(n0 + row) * H + quarter * 8;
    const __nv_bfloat16* bl = g_w1l + (size_t)e * II * H + (size_t)(n0 + row) * H + quarter * 8;
    uint32_t soff = (uint32_t)row * RSB + quarter * 16;

    int warp_m = wid >> 2, warp_n = wid & 3;

    float acc[2][4][4];
    #pragma unroll
    for (int i = 0; i < 2; i++)
        #pragma unroll
        for (int j = 0; j < 4; j++)
            #pragma unroll
            for (int q = 0; q < 4; q++) acc[i][j][q] = 0.f;

    const int NK = H / KC;   // 32

    #pragma unroll
    for (int s = 0; s < STAGES - 1; s++) {
        int ko = s * KC;
        cp16(sb + OFF_T(s, 0) + soff, ah + ko);
        cp16(sb + OFF_T(s, 1) + soff, al + ko);
        cp16(sb + OFF_T(s, 2) + soff, bh + ko);
        cp16(sb + OFF_T(s, 3) + soff, bl + ko);
        cp_commit();
    }

    for (int kc = 0; kc < NK; kc++) {
        cp_wait<STAGES - 2>();
        __syncthreads();
        int kn = kc + STAGES - 1;
        if (kn < NK) {
            int s = kn % STAGES;
            int ko = kn * KC;
            cp16(sb + OFF_T(s, 0) + soff, ah + ko);
            cp16(sb + OFF_T(s, 1) + soff, al + ko);
            cp16(sb + OFF_T(s, 2) + soff, bh + ko);
            cp16(sb + OFF_T(s, 3) + soff, bl + ko);
        }
        cp_commit();
        mma_stage(sb, kc % STAGES, warp_m, warp_n, lane, acc);
    }

    // epilogue: silu + split -> g_hid hi/lo
    int quad = lane >> 2, tq = lane & 3;
    #pragma unroll
    for (int im = 0; im < 2; im++) {
        int mA = m0 + warp_m * 32 + im * 16 + quad;
        int mB = mA + 8;
        bool aA = (mA < cnt), aB = (mB < cnt);
        size_t roA = aA ? (size_t)(base + mA) * II : 0;
        size_t roB = aB ? (size_t)(base + mB) * II : 0;
        #pragma unroll
        for (int in = 0; in < 4; in++) {
            int col = n0 + warp_n * 32 + in * 8 + tq * 2;
            if (aA) {
                float v0 = acc[im][in][0], v1 = acc[im][in][1];
                v0 = v0 / (1.f + __expf(-v0));
                v1 = v1 / (1.f + __expf(-v1));
                uint32_t hi, lo;
                split2(v0, v1, hi, lo);
                *(uint32_t*)(g_hid_hi + roA + col) = hi;
                *(uint32_t*)(g_hid_lo + roA + col) = lo;
            }
            if (aB) {
                float v0 = acc[im][in][2], v1 = acc[im][in][3];
                v0 = v0 / (1.f + __expf(-v0));
                v1 = v1 / (1.f + __expf(-v1));
                uint32_t hi, lo;
                split2(v0, v1, hi, lo);
                *(uint32_t*)(g_hid_hi + roB + col) = hi;
                *(uint32_t*)(g_hid_lo + roB + col) = lo;
            }
        }
    }
}

// ---------------- kernel 3: grouped GEMM2 + scatter-add ----------------
__global__ __launch_bounds__(NTHREADS, 1) void gemm2_tc(float* __restrict__ out) {
    extern __shared__ char smem[];
    int e = blockIdx.z;
    int cnt = g_cnt[e];
    int m0 = blockIdx.y * BM;
    if (m0 >= cnt) return;
    int n0 = blockIdx.x * BN;
    int base = g_off[e];
    int tid = threadIdx.x, wid = tid >> 5, lane = tid & 31;
    uint32_t sb = smem_u32(smem);

    int row = tid >> 2, quarter = tid & 3;
    int am = m0 + row; if (am >= cnt) am = cnt - 1;
    const __nv_bfloat16* ah = g_hid_hi + (size_t)(base + am) * II + quarter * 8;
    const __nv_bfloat16* al = g_hid_lo + (size_t)(base + am) * II + quarter * 8;
    const __nv_bfloat16* bh = g_w2h + (size_t)e * H * II + (size_t)(n0 + row) * II + quarter * 8;
    const __nv_bfloat16* bl = g_w2l + (size_t)e * H * II + (size_t)(n0 + row) * II + quarter * 8;
    uint32_t soff = (uint32_t)row * RSB + quarter * 16;

    int warp_m = wid >> 2, warp_n = wid & 3;

    float acc[2][4][4];
    #pragma unroll
    for (int i = 0; i < 2; i++)
        #pragma unroll
        for (int j = 0; j < 4; j++)
            #pragma unroll
            for (int q = 0; q < 4; q++) acc[i][j][q] = 0.f;

    const int NK = II / KC;  // 128

    #pragma unroll
    for (int s = 0; s < STAGES - 1; s++) {
        int ko = s * KC;
        cp16(sb + OFF_T(s, 0) + soff, ah + ko);
        cp16(sb + OFF_T(s, 1) + soff, al + ko);
        cp16(sb + OFF_T(s, 2) + soff, bh + ko);
        cp16(sb + OFF_T(s, 3) + soff, bl + ko);
        cp_commit();
    }

    for (int kc = 0; kc < NK; kc++) {
        cp_wait<STAGES - 2>();
        __syncthreads();
        int kn = kc + STAGES - 1;
        if (kn < NK) {
            int s = kn % STAGES;
            int ko = kn * KC;
            cp16(sb + OFF_T(s, 0) + soff, ah + ko);
            cp16(sb + OFF_T(s, 1) + soff, al + ko);
            cp16(sb + OFF_T(s, 2) + soff, bh + ko);
            cp16(sb + OFF_T(s, 3) + soff, bl + ko);
        }
        cp_commit();
        mma_stage(sb, kc % STAGES, warp_m, warp_n, lane, acc);
    }

    // epilogue: weighted scatter-add
    int quad = lane >> 2, tq = lane & 3;
    #pragma unroll
    for (int im = 0; im < 2; im++) {
        int mA = m0 + warp_m * 32 + im * 16 + quad;
        int mB = mA + 8;
        bool aA = (mA < cnt), aB = (mB < cnt);
        int tokA = aA ? g_tok[e][mA] : 0;  float wtA = aA ? g_wt[e][mA] : 0.f;
        int tokB = aB ? g_tok[e][mB] : 0;  float wtB = aB ? g_wt[e][mB] : 0.f;
        float* oA = out + (size_t)tokA * H;
        float* oB = out + (size_t)tokB * H;
        #pragma unroll
        for (int in = 0; in < 4; in++) {
            int col = n0 + warp_n * 32 + in * 8 + tq * 2;
            if (aA) {
                atomicAdd(oA + col,     wtA * acc[im][in][0]);
                atomicAdd(oA + col + 1, wtA * acc[im][in][1]);
            }
            if (aB) {
                atomicAdd(oB + col,     wtB * acc[im][in][2]);
                atomicAdd(oB + col + 1, wtB * acc[im][in][3]);
            }
        }
    }
}

// ---------------- launch ----------------
extern "C" void kernel_launch(void* const* d_in, const int* in_sizes, int n_in,
                              void* d_out, int out_size) {
    const float* x  = (const float*)d_in[0];   // [1,2048,1024]
    const float* gw = (const float*)d_in[1];   // [8,1024]
    const float* w1 = (const float*)d_in[2];   // [8,4096,1024]
    const float* w2 = (const float*)d_in[3];   // [8,1024,4096]
    float* out = (float*)d_out;                // [1,2048,1024]

    cudaFuncSetAttribute(gemm1_tc, cudaFuncAttributeMaxDynamicSharedMemorySize, SMEM_TOTAL);
    cudaFuncSetAttribute(gemm2_tc, cudaFuncAttributeMaxDynamicSharedMemorySize, SMEM_TOTAL);

    __nv_bfloat16 *xh, *xl, *w1h, *w1l, *w2h, *w2l;
    cudaGetSymbolAddress((void**)&xh,  g_xh);
    cudaGetSymbolAddress((void**)&xl,  g_xl);
    cudaGetSymbolAddress((void**)&w1h, g_w1h);
    cudaGetSymbolAddress((void**)&w1l, g_w1l);
    cudaGetSymbolAddress((void**)&w2h, g_w2h);
    cudaGetSymbolAddress((void**)&w2l, g_w2l);

    zero_kernel<<<(T * H + 255) / 256, 256>>>(out);
    gate_kernel<<<T, 256>>>(x, gw);
    prefix_kernel<<<1, 32>>>();
    split_kernel<<<(T * H / 4 + 255) / 256, 256>>>(x, xh, xl, T * H / 4);
    split_kernel<<<(E * II * H / 4 + 255) / 256, 256>>>(w1, w1h, w1l, E * II * H / 4);
    split_kernel<<<(E * H * II / 4 + 255) / 256, 256>>>(w2, w2h, w2l, E * H * II / 4);
    gemm1_tc<<<dim3(II / BN, T / BM, E), NTHREADS, SMEM_TOTAL>>>();
    gemm2_tc<<<dim3(H / BN, T / BM, E), NTHREADS, SMEM_TOTAL>>>(out);
}

// round 7
// speedup vs baseline: 1.2894x; 1.2894x over previous
#include <cuda_runtime.h>
#include <cuda_bf16.h>
#include <math.h>
#include <stdint.h>

// Problem constants (B=1)
#define T 2048
#define H 1024
#define II 4096
#define E 8

// Tiling: block 128(M) x 256(N), 8 warps of 64x64
#define BM 128
#define BN 256
#define KC 32              // K elems (bf16) per chunk
#define RSB 80             // smem row stride bytes (64B data + 16B pad)
#define STAGES 3
#define NTHREADS 256

#define ATB (BM * RSB)     // 10240 B per A subtile
#define BTB (BN * RSB)     // 20480 B per B subtile
#define STG_B (2 * ATB + 2 * BTB)              // 61440 B per stage
#define SM_TOK   0
#define SM_TILES 1024
#define OFF_AH(s) (SM_TILES + (s) * STG_B)
#define OFF_AL(s) (SM_TILES + (s) * STG_B + ATB)
#define OFF_BH(s) (SM_TILES + (s) * STG_B + 2 * ATB)
#define OFF_BL(s) (SM_TILES + (s) * STG_B + 2 * ATB + BTB)
#define SMEM_TOTAL (SM_TILES + STAGES * STG_B)   // 185344 B

// ---------------- scratch (device globals) ----------------
__device__ int   g_cnt[E];
__device__ int   g_off[E];
__device__ int   g_tok[E][T];
__device__ float g_wt[E][T];
__device__ __nv_bfloat16 g_xh[(size_t)T * H];
__device__ __nv_bfloat16 g_xl[(size_t)T * H];
__device__ __nv_bfloat16 g_w1h[(size_t)E * II * H];
__device__ __nv_bfloat16 g_w1l[(size_t)E * II * H];
__device__ __nv_bfloat16 g_w2h[(size_t)E * H * II];
__device__ __nv_bfloat16 g_w2l[(size_t)E * H * II];
__device__ __nv_bfloat16 g_hid_hi[(size_t)2 * T * II];
__device__ __nv_bfloat16 g_hid_lo[(size_t)2 * T * II];

// ---------------- helpers ----------------
__device__ __forceinline__ uint32_t smem_u32(const void* p) {
    uint32_t a;
    asm("{ .reg .u64 t; cvta.to.shared.u64 t, %1; cvt.u32.u64 %0, t; }" : "=r"(a) : "l"(p));
    return a;
}
__device__ __forceinline__ void cp16(uint32_t s, const void* g) {
    asm volatile("cp.async.cg.shared.global [%0], [%1], 16;" :: "r"(s), "l"(g));
}
__device__ __forceinline__ void cp_commit() {
    asm volatile("cp.async.commit_group;" ::: "memory");
}
template <int N>
__device__ __forceinline__ void cp_wait() {
    asm volatile("cp.async.wait_group %0;" :: "n"(N) : "memory");
}
__device__ __forceinline__ void ldsm4(uint32_t* r, uint32_t addr) {
    asm volatile("ldmatrix.sync.aligned.m8n8.x4.shared.b16 {%0,%1,%2,%3}, [%4];"
                 : "=r"(r[0]), "=r"(r[1]), "=r"(r[2]), "=r"(r[3]) : "r"(addr));
}
__device__ __forceinline__ void mma16816(float* d, const uint32_t* a, const uint32_t* b) {
    asm volatile("mma.sync.aligned.m16n8k16.row.col.f32.bf16.bf16.f32 "
                 "{%0,%1,%2,%3}, {%4,%5,%6,%7}, {%8,%9}, {%0,%1,%2,%3};"
                 : "+f"(d[0]), "+f"(d[1]), "+f"(d[2]), "+f"(d[3])
                 : "r"(a[0]), "r"(a[1]), "r"(a[2]), "r"(a[3]), "r"(b[0]), "r"(b[1]));
}
__device__ __forceinline__ void split4(float4 v, uint2& hi, uint2& lo) {
    float f0 = v.x, f1 = v.y, f2 = v.z, f3 = v.w;
    unsigned h0 = __bfloat16_as_ushort(__float2bfloat16(f0));
    unsigned h1 = __bfloat16_as_ushort(__float2bfloat16(f1));
    unsigned h2 = __bfloat16_as_ushort(__float2bfloat16(f2));
    unsigned h3 = __bfloat16_as_ushort(__float2bfloat16(f3));
    float r0 = f0 - __bfloat162float(__ushort_as_bfloat16((unsigned short)h0));
    float r1 = f1 - __bfloat162float(__ushort_as_bfloat16((unsigned short)h1));
    float r2 = f2 - __bfloat162float(__ushort_as_bfloat16((unsigned short)h2));
    float r3 = f3 - __bfloat162float(__ushort_as_bfloat16((unsigned short)h3));
    unsigned l0 = __bfloat16_as_ushort(__float2bfloat16(r0));
    unsigned l1 = __bfloat16_as_ushort(__float2bfloat16(r1));
    unsigned l2 = __bfloat16_as_ushort(__float2bfloat16(r2));
    unsigned l3 = __bfloat16_as_ushort(__float2bfloat16(r3));
    hi.x = h0 | (h1 << 16); hi.y = h2 | (h3 << 16);
    lo.x = l0 | (l1 << 16); lo.y = l2 | (l3 << 16);
}
__device__ __forceinline__ void split2(float a, float b, uint32_t& hi, uint32_t& lo) {
    unsigned ha = __bfloat16_as_ushort(__float2bfloat16(a));
    unsigned hb = __bfloat16_as_ushort(__float2bfloat16(b));
    float ra = a - __bfloat162float(__ushort_as_bfloat16((unsigned short)ha));
    float rb = b - __bfloat162float(__ushort_as_bfloat16((unsigned short)hb));
    unsigned la = __bfloat16_as_ushort(__float2bfloat16(ra));
    unsigned lb = __bfloat16_as_ushort(__float2bfloat16(rb));
    hi = ha | (hb << 16);
    lo = la | (lb << 16);
}

// ---------------- kernel: fp32 -> bf16 hi/lo split ----------------
__global__ void split_kernel(const float* __restrict__ src,
                             __nv_bfloat16* __restrict__ hi,
                             __nv_bfloat16* __restrict__ lo, int n4) {
    int i = blockIdx.x * blockDim.x + threadIdx.x;
    if (i < n4) {
        float4 v = ((const float4*)src)[i];
        uint2 h, l;
        split4(v, h, l);
        ((uint2*)hi)[i] = h;
        ((uint2*)lo)[i] = l;
    }
}

// ---------------- kernel 0: zero output + counters ----------------
__global__ void zero_kernel(float* __restrict__ out) {
    int i = blockIdx.x * blockDim.x + threadIdx.x;
    if (i < T * H) out[i] = 0.f;
    if (i < E) g_cnt[i] = 0;
}

// ---------------- kernel 1: gate -> top2 -> grouped lists ----------------
__global__ __launch_bounds__(256) void gate_kernel(const float* __restrict__ x,
                                                   const float* __restrict__ gw) {
    int t = blockIdx.x;
    int warp = threadIdx.x >> 5;
    int lane = threadIdx.x & 31;

    const float4* xr = (const float4*)(x + (size_t)t * H);
    const float4* gr = (const float4*)(gw + (size_t)warp * H);
    float s = 0.f;
    for (int j = lane; j < H / 4; j += 32) {
        float4 a = xr[j], b = gr[j];
        s += a.x * b.x + a.y * b.y + a.z * b.z + a.w * b.w;
    }
    #pragma unroll
    for (int o = 16; o > 0; o >>= 1) s += __shfl_xor_sync(0xffffffffu, s, o);

    __shared__ float lg[E];
    if (lane == 0) lg[warp] = s;
    __syncthreads();

    if (threadIdx.x == 0) {
        int e0 = 0;
        #pragma unroll
        for (int e = 1; e < E; e++) if (lg[e] > lg[e0]) e0 = e;
        int e1 = -1;
        #pragma unroll
        for (int e = 0; e < E; e++) {
            if (e == e0) continue;
            if (e1 < 0 || lg[e] > lg[e1]) e1 = e;
        }
        float d = expf(lg[e1] - lg[e0]);
        float w0 = 1.f / (1.f + d);
        float w1v = d / (1.f + d);
        int p0 = atomicAdd(&g_cnt[e0], 1);
        g_tok[e0][p0] = t; g_wt[e0][p0] = w0;
        int p1 = atomicAdd(&g_cnt[e1], 1);
        g_tok[e1][p1] = t; g_wt[e1][p1] = w1v;
    }
}

__global__ void prefix_kernel() {
    if (threadIdx.x == 0 && blockIdx.x == 0) {
        int acc = 0;
        #pragma unroll
        for (int e = 0; e < E; e++) { g_off[e] = acc; acc += g_cnt[e]; }
    }
}

// ---------------- mainloop mma over one stage (64x64 warp tile) ----------------
__device__ __forceinline__ void mma_stage(uint32_t sb, int stage, int warp_m, int warp_n,
                                          int lane, float (*acc)[8][4]) {
    int lr = lane & 15;
    uint32_t lc16 = (lane >> 4) * 16;
    uint32_t ah_b = sb + OFF_AH(stage), al_b = sb + OFF_AL(stage);
    uint32_t bh_b = sb + OFF_BH(stage), bl_b = sb + OFF_BL(stage);
    #pragma unroll
    for (int kk = 0; kk < 2; kk++) {
        uint32_t colb = kk * 32 + lc16;
        uint32_t Ah[4][4], Al[4][4];
        #pragma unroll
        for (int im = 0; im < 4; im++) {
            uint32_t aoff = (uint32_t)(warp_m * 64 + im * 16 + lr) * RSB + colb;
            ldsm4(Ah[im], ah_b + aoff);
            ldsm4(Al[im], al_b + aoff);
        }
        #pragma unroll
        for (int in2 = 0; in2 < 4; in2++) {
            uint32_t boff = (uint32_t)(warp_n * 64 + in2 * 16 + lr) * RSB + colb;
            uint32_t th[4], tl[4];
            ldsm4(th, bh_b + boff);
            ldsm4(tl, bl_b + boff);
            uint32_t Bh0[2] = {th[0], th[2]}, Bh1[2] = {th[1], th[3]};
            uint32_t Bl0[2] = {tl[0], tl[2]}, Bl1[2] = {tl[1], tl[3]};
            #pragma unroll
            for (int im = 0; im < 4; im++) {
                float* a0 = acc[im][2 * in2];
                float* a1 = acc[im][2 * in2 + 1];
                mma16816(a0, Ah[im], Bh0);
                mma16816(a0, Ah[im], Bl0);
                mma16816(a0, Al[im], Bh0);
                mma16816(a1, Ah[im], Bh1);
                mma16816(a1, Ah[im], Bl1);
                mma16816(a1, Al[im], Bh1);
            }
        }
    }
}

// ---------------- kernel 2: grouped GEMM1 + silu ----------------
__global__ __launch_bounds__(NTHREADS, 1) void gemm1_tc() {
    extern __shared__ char smem[];
    int e = blockIdx.z;
    int cnt = g_cnt[e];
    int m0 = blockIdx.y * BM;
    if (m0 >= cnt) return;
    int n0 = blockIdx.x * BN;
    int base = g_off[e];
    int tid = threadIdx.x, wid = tid >> 5, lane = tid & 31;

    int* stok = (int*)(smem + SM_TOK);
    if (tid < BM) {
        int m = m0 + tid;
        stok[tid] = g_tok[e][m < cnt ? m : cnt - 1];
    }
    __syncthreads();
    uint32_t sb = smem_u32(smem);

    // A staging: row = tid/2 (0..127), half = tid&1 -> 32B (two cp16) per subtile
    int arow = tid >> 1, ahalf = tid & 1;
    const __nv_bfloat16* pah = g_xh + (size_t)stok[arow] * H + ahalf * 16;
    const __nv_bfloat16* pal = g_xl + (size_t)stok[arow] * H + ahalf * 16;
    uint32_t soffA = (uint32_t)arow * RSB + ahalf * 32;
    // B staging: row = tid (0..255) -> full 64B row (four cp16) per subtile
    const __nv_bfloat16* pbh = g_w1h + (size_t)e * II * H + (size_t)(n0 + tid) * H;
    const __nv_bfloat16* pbl = g_w1l + (size_t)e * II * H + (size_t)(n0 + tid) * H;
    uint32_t soffB = (uint32_t)tid * RSB;

    int warp_m = wid >> 2, warp_n = wid & 3;

    float acc[4][8][4];
    #pragma unroll
    for (int i = 0; i < 4; i++)
        #pragma unroll
        for (int j = 0; j < 8; j++)
            #pragma unroll
            for (int q = 0; q < 4; q++) acc[i][j][q] = 0.f;

    const int NK = H / KC;   // 32

    #pragma unroll
    for (int s = 0; s < STAGES - 1; s++) {
        int ko = s * KC;
        cp16(sb + OFF_AH(s) + soffA,      pah + ko);
        cp16(sb + OFF_AH(s) + soffA + 16, pah + ko + 8);
        cp16(sb + OFF_AL(s) + soffA,      pal + ko);
        cp16(sb + OFF_AL(s) + soffA + 16, pal + ko + 8);
        #pragma unroll
        for (int j = 0; j < 4; j++) {
            cp16(sb + OFF_BH(s) + soffB + j * 16, pbh + ko + j * 8);
            cp16(sb + OFF_BL(s) + soffB + j * 16, pbl + ko + j * 8);
        }
        cp_commit();
    }

    for (int kc = 0; kc < NK; kc++) {
        cp_wait<STAGES - 2>();
        __syncthreads();
        int kn = kc + STAGES - 1;
        if (kn < NK) {
            int s = kn % STAGES;
            int ko = kn * KC;
            cp16(sb + OFF_AH(s) + soffA,      pah + ko);
            cp16(sb + OFF_AH(s) + soffA + 16, pah + ko + 8);
            cp16(sb + OFF_AL(s) + soffA,      pal + ko);
            cp16(sb + OFF_AL(s) + soffA + 16, pal + ko + 8);
            #pragma unroll
            for (int j = 0; j < 4; j++) {
                cp16(sb + OFF_BH(s) + soffB + j * 16, pbh + ko + j * 8);
                cp16(sb + OFF_BL(s) + soffB + j * 16, pbl + ko + j * 8);
            }
        }
        cp_commit();
        mma_stage(sb, kc % STAGES, warp_m, warp_n, lane, acc);
    }

    // epilogue: silu + split -> g_hid hi/lo
    int quad = lane >> 2, tq = lane & 3;
    #pragma unroll
    for (int im = 0; im < 4; im++) {
        int mA = m0 + warp_m * 64 + im * 16 + quad;
        int mB = mA + 8;
        bool aA = (mA < cnt), aB = (mB < cnt);
        size_t roA = aA ? (size_t)(base + mA) * II : 0;
        size_t roB = aB ? (size_t)(base + mB) * II : 0;
        #pragma unroll
        for (int in = 0; in < 8; in++) {
            int col = n0 + warp_n * 64 + in * 8 + tq * 2;
            if (aA) {
                float v0 = acc[im][in][0], v1 = acc[im][in][1];
                v0 = v0 / (1.f + __expf(-v0));
                v1 = v1 / (1.f + __expf(-v1));
                uint32_t hi, lo;
                split2(v0, v1, hi, lo);
                *(uint32_t*)(g_hid_hi + roA + col) = hi;
                *(uint32_t*)(g_hid_lo + roA + col) = lo;
            }
            if (aB) {
                float v0 = acc[im][in][2], v1 = acc[im][in][3];
                v0 = v0 / (1.f + __expf(-v0));
                v1 = v1 / (1.f + __expf(-v1));
                uint32_t hi, lo;
                split2(v0, v1, hi, lo);
                *(uint32_t*)(g_hid_hi + roB + col) = hi;
                *(uint32_t*)(g_hid_lo + roB + col) = lo;
            }
        }
    }
}

// ---------------- kernel 3: grouped GEMM2 + scatter-add ----------------
__global__ __launch_bounds__(NTHREADS, 1) void gemm2_tc(float* __restrict__ out) {
    extern __shared__ char smem[];
    int e = blockIdx.z;
    int cnt = g_cnt[e];
    int m0 = blockIdx.y * BM;
    if (m0 >= cnt) return;
    int n0 = blockIdx.x * BN;
    int base = g_off[e];
    int tid = threadIdx.x, wid = tid >> 5, lane = tid & 31;
    uint32_t sb = smem_u32(smem);

    int arow = tid >> 1, ahalf = tid & 1;
    int am = m0 + arow; if (am >= cnt) am = cnt - 1;
    const __nv_bfloat16* pah = g_hid_hi + (size_t)(base + am) * II + ahalf * 16;
    const __nv_bfloat16* pal = g_hid_lo + (size_t)(base + am) * II + ahalf * 16;
    uint32_t soffA = (uint32_t)arow * RSB + ahalf * 32;
    const __nv_bfloat16* pbh = g_w2h + (size_t)e * H * II + (size_t)(n0 + tid) * II;
    const __nv_bfloat16* pbl = g_w2l + (size_t)e * H * II + (size_t)(n0 + tid) * II;
    uint32_t soffB = (uint32_t)tid * RSB;

    int warp_m = wid >> 2, warp_n = wid & 3;

    float acc[4][8][4];
    #pragma unroll
    for (int i = 0; i < 4; i++)
        #pragma unroll
        for (int j = 0; j < 8; j++)
            #pragma unroll
            for (int q = 0; q < 4; q++) acc[i][j][q] = 0.f;

    const int NK = II / KC;  // 128

    #pragma unroll
    for (int s = 0; s < STAGES - 1; s++) {
        int ko = s * KC;
        cp16(sb + OFF_AH(s) + soffA,      pah + ko);
        cp16(sb + OFF_AH(s) + soffA + 16, pah + ko + 8);
        cp16(sb + OFF_AL(s) + soffA,      pal + ko);
        cp16(sb + OFF_AL(s) + soffA + 16, pal + ko + 8);
        #pragma unroll
        for (int j = 0; j < 4; j++) {
            cp16(sb + OFF_BH(s) + soffB + j * 16, pbh + ko + j * 8);
            cp16(sb + OFF_BL(s) + soffB + j * 16, pbl + ko + j * 8);
        }
        cp_commit();
    }

    for (int kc = 0; kc < NK; kc++) {
        cp_wait<STAGES - 2>();
        __syncthreads();
        int kn = kc + STAGES - 1;
        if (kn < NK) {
            int s = kn % STAGES;
            int ko = kn * KC;
            cp16(sb + OFF_AH(s) + soffA,      pah + ko);
            cp16(sb + OFF_AH(s) + soffA + 16, pah + ko + 8);
            cp16(sb + OFF_AL(s) + soffA,      pal + ko);
            cp16(sb + OFF_AL(s) + soffA + 16, pal + ko + 8);
            #pragma unroll
            for (int j = 0; j < 4; j++) {
                cp16(sb + OFF_BH(s) + soffB + j * 16, pbh + ko + j * 8);
                cp16(sb + OFF_BL(s) + soffB + j * 16, pbl + ko + j * 8);
            }
        }
        cp_commit();
        mma_stage(sb, kc % STAGES, warp_m, warp_n, lane, acc);
    }

    // epilogue: weighted scatter-add
    int quad = lane >> 2, tq = lane & 3;
    #pragma unroll
    for (int im = 0; im < 4; im++) {
        int mA = m0 + warp_m * 64 + im * 16 + quad;
        int mB = mA + 8;
        bool aA = (mA < cnt), aB = (mB < cnt);
        int tokA = aA ? g_tok[e][mA] : 0;  float wtA = aA ? g_wt[e][mA] : 0.f;
        int tokB = aB ? g_tok[e][mB] : 0;  float wtB = aB ? g_wt[e][mB] : 0.f;
        float* oA = out + (size_t)tokA * H;
        float* oB = out + (size_t)tokB * H;
        #pragma unroll
        for (int in = 0; in < 8; in++) {
            int col = n0 + warp_n * 64 + in * 8 + tq * 2;
            if (aA) {
                atomicAdd(oA + col,     wtA * acc[im][in][0]);
                atomicAdd(oA + col + 1, wtA * acc[im][in][1]);
            }
            if (aB) {
                atomicAdd(oB + col,     wtB * acc[im][in][2]);
                atomicAdd(oB + col + 1, wtB * acc[im][in][3]);
            }
        }
    }
}

// ---------------- launch ----------------
extern "C" void kernel_launch(void* const* d_in, const int* in_sizes, int n_in,
                              void* d_out, int out_size) {
    const float* x  = (const float*)d_in[0];   // [1,2048,1024]
    const float* gw = (const float*)d_in[1];   // [8,1024]
    const float* w1 = (const float*)d_in[2];   // [8,4096,1024]
    const float* w2 = (const float*)d_in[3];   // [8,1024,4096]
    float* out = (float*)d_out;                // [1,2048,1024]

    cudaFuncSetAttribute(gemm1_tc, cudaFuncAttributeMaxDynamicSharedMemorySize, SMEM_TOTAL);
    cudaFuncSetAttribute(gemm2_tc, cudaFuncAttributeMaxDynamicSharedMemorySize, SMEM_TOTAL);

    __nv_bfloat16 *xh, *xl, *w1h, *w1l, *w2h, *w2l;
    cudaGetSymbolAddress((void**)&xh,  g_xh);
    cudaGetSymbolAddress((void**)&xl,  g_xl);
    cudaGetSymbolAddress((void**)&w1h, g_w1h);
    cudaGetSymbolAddress((void**)&w1l, g_w1l);
    cudaGetSymbolAddress((void**)&w2h, g_w2h);
    cudaGetSymbolAddress((void**)&w2l, g_w2l);

    zero_kernel<<<(T * H + 255) / 256, 256>>>(out);
    gate_kernel<<<T, 256>>>(x, gw);
    prefix_kernel<<<1, 32>>>();
    split_kernel<<<(T * H / 4 + 255) / 256, 256>>>(x, xh, xl, T * H / 4);
    split_kernel<<<(E * II * H / 4 + 255) / 256, 256>>>(w1, w1h, w1l, E * II * H / 4);
    split_kernel<<<(E * H * II / 4 + 255) / 256, 256>>>(w2, w2h, w2l, E * H * II / 4);
    gemm1_tc<<<dim3(II / BN, T / BM, E), NTHREADS, SMEM_TOTAL>>>();
    gemm2_tc<<<dim3(H / BN, T / BM, E), NTHREADS, SMEM_TOTAL>>>(out);
}

// round 10
// speedup vs baseline: 2.8437x; 2.2054x over previous
#include <cuda_runtime.h>
#include <cuda_fp16.h>
#include <math.h>
#include <stdint.h>

// Problem constants (B=1)
#define T 2048
#define H 1024
#define II 4096
#define E 8

// Tiling: block 128(M) x 256(N), 8 warps of 64x64, fp16 single-term
#define BM 128
#define BN 256
#define KC 32              // K elems (fp16) per chunk
#define RSB 80             // smem row stride bytes (64B data + 16B pad)
#define STAGES 4
#define NTHREADS 256

#define ATB (BM * RSB)     // 10240 B
#define BTB (BN * RSB)     // 20480 B
#define STG_B (ATB + BTB)  // 30720 B per stage
#define SM_TOK   0
#define SM_TILES 1024
#define OFF_A(s) (SM_TILES + (s) * STG_B)
#define OFF_B(s) (SM_TILES + (s) * STG_B + ATB)
#define SMEM_TOTAL (SM_TILES + STAGES * STG_B)   // 123904 B

// ---------------- scratch (device globals) ----------------
__device__ int   g_cnt[E];
__device__ int   g_off[E];
__device__ int   g_tok[E][T];
__device__ float g_wt[E][T];
__device__ __half g_xh[(size_t)T * H];
__device__ __half g_w1h[(size_t)E * II * H];
__device__ __half g_w2h[(size_t)E * H * II];
__device__ __half g_hid[(size_t)2 * T * II];

// ---------------- helpers ----------------
__device__ __forceinline__ uint32_t smem_u32(const void* p) {
    uint32_t a;
    asm("{ .reg .u64 t; cvta.to.shared.u64 t, %1; cvt.u32.u64 %0, t; }" : "=r"(a) : "l"(p));
    return a;
}
__device__ __forceinline__ void cp16(uint32_t s, const void* g) {
    asm volatile("cp.async.cg.shared.global [%0], [%1], 16;" :: "r"(s), "l"(g));
}
__device__ __forceinline__ void cp_commit() {
    asm volatile("cp.async.commit_group;" ::: "memory");
}
template <int N>
__device__ __forceinline__ void cp_wait() {
    asm volatile("cp.async.wait_group %0;" :: "n"(N) : "memory");
}
__device__ __forceinline__ void ldsm4(uint32_t* r, uint32_t addr) {
    asm volatile("ldmatrix.sync.aligned.m8n8.x4.shared.b16 {%0,%1,%2,%3}, [%4];"
                 : "=r"(r[0]), "=r"(r[1]), "=r"(r[2]), "=r"(r[3]) : "r"(addr));
}
__device__ __forceinline__ void mma16816(float* d, const uint32_t* a, const uint32_t* b) {
    asm volatile("mma.sync.aligned.m16n8k16.row.col.f32.f16.f16.f32 "
                 "{%0,%1,%2,%3}, {%4,%5,%6,%7}, {%8,%9}, {%0,%1,%2,%3};"
                 : "+f"(d[0]), "+f"(d[1]), "+f"(d[2]), "+f"(d[3])
                 : "r"(a[0]), "r"(a[1]), "r"(a[2]), "r"(a[3]), "r"(b[0]), "r"(b[1]));
}
__device__ __forceinline__ uint32_t pack_h2(float a, float b) {
    __half2 h = __floats2half2_rn(a, b);
    return *(uint32_t*)&h;
}

// ---------------- kernel: fp32 -> fp16 convert (one elem4 per thread, like split_kernel) ----------------
__global__ void cvt_kernel(const float* __restrict__ src,
                           __half* __restrict__ dst, int n4) {
    int i = blockIdx.x * blockDim.x + threadIdx.x;
    if (i < n4) {
        float4 v = ((const float4*)src)[i];
        uint2 u;
        u.x = pack_h2(v.x, v.y);
        u.y = pack_h2(v.z, v.w);
        ((uint2*)dst)[i] = u;
    }
}

// ---------------- kernel 0: zero output + counters ----------------
__global__ void zero_kernel(float* __restrict__ out) {
    int i = blockIdx.x * blockDim.x + threadIdx.x;
    if (i < T * H) out[i] = 0.f;
    if (i < E) g_cnt[i] = 0;
}

// ---------------- kernel 1: gate -> top2 -> grouped lists ----------------
__global__ __launch_bounds__(256) void gate_kernel(const float* __restrict__ x,
                                                   const float* __restrict__ gw) {
    int t = blockIdx.x;
    int warp = threadIdx.x >> 5;
    int lane = threadIdx.x & 31;

    const float4* xr = (const float4*)(x + (size_t)t * H);
    const float4* gr = (const float4*)(gw + (size_t)warp * H);
    float s = 0.f;
    for (int j = lane; j < H / 4; j += 32) {
        float4 a = xr[j], b = gr[j];
        s += a.x * b.x + a.y * b.y + a.z * b.z + a.w * b.w;
    }
    #pragma unroll
    for (int o = 16; o > 0; o >>= 1) s += __shfl_xor_sync(0xffffffffu, s, o);

    __shared__ float lg[E];
    if (lane == 0) lg[warp] = s;
    __syncthreads();

    if (threadIdx.x == 0) {
        int e0 = 0;
        #pragma unroll
        for (int e = 1; e < E; e++) if (lg[e] > lg[e0]) e0 = e;
        int e1 = -1;
        #pragma unroll
        for (int e = 0; e < E; e++) {
            if (e == e0) continue;
            if (e1 < 0 || lg[e] > lg[e1]) e1 = e;
        }
        float d = expf(lg[e1] - lg[e0]);
        float w0 = 1.f / (1.f + d);
        float w1v = d / (1.f + d);
        int p0 = atomicAdd(&g_cnt[e0], 1);
        g_tok[e0][p0] = t; g_wt[e0][p0] = w0;
        int p1 = atomicAdd(&g_cnt[e1], 1);
        g_tok[e1][p1] = t; g_wt[e1][p1] = w1v;
    }
}

// ---------------- kernel 1b: exclusive prefix ----------------
__global__ void prefix_kernel() {
    if (threadIdx.x == 0 && blockIdx.x == 0) {
        int acc = 0;
        #pragma unroll
        for (int e = 0; e < E; e++) { g_off[e] = acc; acc += g_cnt[e]; }
    }
}

// ---------------- mainloop mma over one stage (64x64 warp tile, fp16) ----------------
__device__ __forceinline__ void mma_stage(uint32_t sb, int stage, int warp_m, int warp_n,
                                          int lane, float (*acc)[8][4]) {
    int lr = lane & 15;
    uint32_t lc16 = (lane >> 4) * 16;
    uint32_t a_b = sb + OFF_A(stage), b_b = sb + OFF_B(stage);
    #pragma unroll
    for (int kk = 0; kk < 2; kk++) {
        uint32_t colb = kk * 32 + lc16;
        uint32_t A[4][4];
        #pragma unroll
        for (int im = 0; im < 4; im++) {
            uint32_t aoff = (uint32_t)(warp_m * 64 + im * 16 + lr) * RSB + colb;
            ldsm4(A[im], a_b + aoff);
        }
        #pragma unroll
        for (int in2 = 0; in2 < 4; in2++) {
            uint32_t boff = (uint32_t)(warp_n * 64 + in2 * 16 + lr) * RSB + colb;
            uint32_t t[4];
            ldsm4(t, b_b + boff);
            uint32_t B0[2] = {t[0], t[2]}, B1[2] = {t[1], t[3]};
            #pragma unroll
            for (int im = 0; im < 4; im++) {
                mma16816(acc[im][2 * in2],     A[im], B0);
                mma16816(acc[im][2 * in2 + 1], A[im], B1);
            }
        }
    }
}

// ---------------- kernel 2: grouped GEMM1 + silu ----------------
__global__ __launch_bounds__(NTHREADS, 1) void gemm1_tc() {
    extern __shared__ char smem[];
    int e = blockIdx.z;
    int cnt = g_cnt[e];
    int m0 = blockIdx.y * BM;
    if (m0 >= cnt) return;
    int n0 = blockIdx.x * BN;
    int base = g_off[e];
    int tid = threadIdx.x, wid = tid >> 5, lane = tid & 31;

    int* stok = (int*)(smem + SM_TOK);
    if (tid < BM) {
        int m = m0 + tid;
        stok[tid] = g_tok[e][m < cnt ? m : cnt - 1];
    }
    __syncthreads();
    uint32_t sb = smem_u32(smem);

    // A staging: row = tid/2 (0..127), half = tid&1 -> 32B (two cp16)
    int arow = tid >> 1, ahalf = tid & 1;
    const __half* pa = g_xh + (size_t)stok[arow] * H + ahalf * 16;
    uint32_t soffA = (uint32_t)arow * RSB + ahalf * 32;
    // B staging: row = tid (0..255) -> full 64B row (four cp16)
    const __half* pb = g_w1h + (size_t)e * II * H + (size_t)(n0 + tid) * H;
    uint32_t soffB = (uint32_t)tid * RSB;

    int warp_m = wid >> 2, warp_n = wid & 3;

    float acc[4][8][4];
    #pragma unroll
    for (int i = 0; i < 4; i++)
        #pragma unroll
        for (int j = 0; j < 8; j++)
            #pragma unroll
            for (int q = 0; q < 4; q++) acc[i][j][q] = 0.f;

    const int NK = H / KC;   // 32

    #pragma unroll
    for (int s = 0; s < STAGES - 1; s++) {
        int ko = s * KC;
        cp16(sb + OFF_A(s) + soffA,      pa + ko);
        cp16(sb + OFF_A(s) + soffA + 16, pa + ko + 8);
        #pragma unroll
        for (int j = 0; j < 4; j++)
            cp16(sb + OFF_B(s) + soffB + j * 16, pb + ko + j * 8);
        cp_commit();
    }

    for (int kc = 0; kc < NK; kc++) {
        cp_wait<STAGES - 2>();
        __syncthreads();
        int kn = kc + STAGES - 1;
        if (kn < NK) {
            int s = kn % STAGES;
            int ko = kn * KC;
            cp16(sb + OFF_A(s) + soffA,      pa + ko);
            cp16(sb + OFF_A(s) + soffA + 16, pa + ko + 8);
            #pragma unroll
            for (int j = 0; j < 4; j++)
                cp16(sb + OFF_B(s) + soffB + j * 16, pb + ko + j * 8);
        }
        cp_commit();
        mma_stage(sb, kc % STAGES, warp_m, warp_n, lane, acc);
    }

    // epilogue: silu -> fp16 hid
    int quad = lane >> 2, tq = lane & 3;
    #pragma unroll
    for (int im = 0; im < 4; im++) {
        int mA = m0 + warp_m * 64 + im * 16 + quad;
        int mB = mA + 8;
        bool aA = (mA < cnt), aB = (mB < cnt);
        size_t roA = aA ? (size_t)(base + mA) * II : 0;
        size_t roB = aB ? (size_t)(base + mB) * II : 0;
        #pragma unroll
        for (int in = 0; in < 8; in++) {
            int col = n0 + warp_n * 64 + in * 8 + tq * 2;
            if (aA) {
                float v0 = acc[im][in][0], v1 = acc[im][in][1];
                v0 = v0 / (1.f + __expf(-v0));
                v1 = v1 / (1.f + __expf(-v1));
                *(uint32_t*)(g_hid + roA + col) = pack_h2(v0, v1);
            }
            if (aB) {
                float v0 = acc[im][in][2], v1 = acc[im][in][3];
                v0 = v0 / (1.f + __expf(-v0));
                v1 = v1 / (1.f + __expf(-v1));
                *(uint32_t*)(g_hid + roB + col) = pack_h2(v0, v1);
            }
        }
    }
}

// ---------------- kernel 3: grouped GEMM2 + scatter-add ----------------
__global__ __launch_bounds__(NTHREADS, 1) void gemm2_tc(float* __restrict__ out) {
    extern __shared__ char smem[];
    int e = blockIdx.z;
    int cnt = g_cnt[e];
    int m0 = blockIdx.y * BM;
    if (m0 >= cnt) return;
    int n0 = blockIdx.x * BN;
    int base = g_off[e];
    int tid = threadIdx.x, wid = tid >> 5, lane = tid & 31;
    uint32_t sb = smem_u32(smem);

    int arow = tid >> 1, ahalf = tid & 1;
    int am = m0 + arow; if (am >= cnt) am = cnt - 1;
    const __half* pa = g_hid + (size_t)(base + am) * II + ahalf * 16;
    uint32_t soffA = (uint32_t)arow * RSB + ahalf * 32;
    const __half* pb = g_w2h + (size_t)e * H * II + (size_t)(n0 + tid) * II;
    uint32_t soffB = (uint32_t)tid * RSB;

    int warp_m = wid >> 2, warp_n = wid & 3;

    float acc[4][8][4];
    #pragma unroll
    for (int i = 0; i < 4; i++)
        #pragma unroll
        for (int j = 0; j < 8; j++)
            #pragma unroll
            for (int q = 0; q < 4; q++) acc[i][j][q] = 0.f;

    const int NK = II / KC;  // 128

    #pragma unroll
    for (int s = 0; s < STAGES - 1; s++) {
        int ko = s * KC;
        cp16(sb + OFF_A(s) + soffA,      pa + ko);
        cp16(sb + OFF_A(s) + soffA + 16, pa + ko + 8);
        #pragma unroll
        for (int j = 0; j < 4; j++)
            cp16(sb + OFF_B(s) + soffB + j * 16, pb + ko + j * 8);
        cp_commit();
    }

    for (int kc = 0; kc < NK; kc++) {
        cp_wait<STAGES - 2>();
        __syncthreads();
        int kn = kc + STAGES - 1;
        if (kn < NK) {
            int s = kn % STAGES;
            int ko = kn * KC;
            cp16(sb + OFF_A(s) + soffA,      pa + ko);
            cp16(sb + OFF_A(s) + soffA + 16, pa + ko + 8);
            #pragma unroll
            for (int j = 0; j < 4; j++)
                cp16(sb + OFF_B(s) + soffB + j * 16, pb + ko + j * 8);
        }
        cp_commit();
        mma_stage(sb, kc % STAGES, warp_m, warp_n, lane, acc);
    }

    // epilogue: weighted scatter-add
    int quad = lane >> 2, tq = lane & 3;
    #pragma unroll
    for (int im = 0; im < 4; im++) {
        int mA = m0 + warp_m * 64 + im * 16 + quad;
        int mB = mA + 8;
        bool aA = (mA < cnt), aB = (mB < cnt);
        int tokA = aA ? g_tok[e][mA] : 0;  float wtA = aA ? g_wt[e][mA] : 0.f;
        int tokB = aB ? g_tok[e][mB] : 0;  float wtB = aB ? g_wt[e][mB] : 0.f;
        float* oA = out + (size_t)tokA * H;
        float* oB = out + (size_t)tokB * H;
        #pragma unroll
        for (int in = 0; in < 8; in++) {
            int col = n0 + warp_n * 64 + in * 8 + tq * 2;
            if (aA) {
                atomicAdd(oA + col,     wtA * acc[im][in][0]);
                atomicAdd(oA + col + 1, wtA * acc[im][in][1]);
            }
            if (aB) {
                atomicAdd(oB + col,     wtB * acc[im][in][2]);
                atomicAdd(oB + col + 1, wtB * acc[im][in][3]);
            }
        }
    }
}

// ---------------- launch ----------------
extern "C" void kernel_launch(void* const* d_in, const int* in_sizes, int n_in,
                              void* d_out, int out_size) {
    const float* x  = (const float*)d_in[0];   // [1,2048,1024]
    const float* gw = (const float*)d_in[1];   // [8,1024]
    const float* w1 = (const float*)d_in[2];   // [8,4096,1024]
    const float* w2 = (const float*)d_in[3];   // [8,1024,4096]
    float* out = (float*)d_out;                // [1,2048,1024]

    cudaFuncSetAttribute(gemm1_tc, cudaFuncAttributeMaxDynamicSharedMemorySize, SMEM_TOTAL);
    cudaFuncSetAttribute(gemm2_tc, cudaFuncAttributeMaxDynamicSharedMemorySize, SMEM_TOTAL);

    __half *xh, *w1h, *w2h;
    cudaGetSymbolAddress((void**)&xh,  g_xh);
    cudaGetSymbolAddress((void**)&w1h, g_w1h);
    cudaGetSymbolAddress((void**)&w2h, g_w2h);

    zero_kernel<<<(T * H + 255) / 256, 256>>>(out);
    gate_kernel<<<T, 256>>>(x, gw);
    prefix_kernel<<<1, 32>>>();
    cvt_kernel<<<(T * H / 4 + 255) / 256, 256>>>(x, xh, T * H / 4);
    cvt_kernel<<<(E * II * H / 4 + 255) / 256, 256>>>(w1, w1h, E * II * H / 4);
    cvt_kernel<<<(E * H * II / 4 + 255) / 256, 256>>>(w2, w2h, E * H * II / 4);
    gemm1_tc<<<dim3(II / BN, T / BM, E), NTHREADS, SMEM_TOTAL>>>();
    gemm2_tc<<<dim3(H / BN, T / BM, E), NTHREADS, SMEM_TOTAL>>>(out);
}